// round 10
// baseline (speedup 1.0000x reference)
#include <cuda_runtime.h>
#include <stdint.h>

#define NSTAGE 2
#define CH_ELEMS 4096u   // one 16KB chunk: [2 kt][16 ntp][32 lane][4 w] tf32 (k16 slab)
#define CH_BYTES 16384u

// dynamic smem layout (bytes)
// mbars: ringA full[2]@0,16  ringA empty[2]@32,48  ringB full[2]@64,80  ringB empty[2]@96,112
#define OFF_T 128u                                // t_range 25 f32
#define OFF_BW 384u                               // float2 (b1, wt)[256] -> 2048B
#define OFF_B2 2432u                              // f32 b2[256] -> 1024B
#define OFF_ZH_A 3584u                            // 64x256 tf32 A-frag order = 65536B
#define OFF_ZH_B (OFF_ZH_A + 65536u)              // 69120
#define OFF_RING_A (OFF_ZH_B + 65536u)            // 134656
#define OFF_RING_B (OFF_RING_A + NSTAGE * CH_BYTES)  // 167424
#define DYN_SMEM (OFF_RING_B + NSTAGE * CH_BYTES)    // 200192

// prep output: 32 chunks (W1 slabs 0-15, W2 slabs 16-31) of 16KB, B-frag uint4-pair order
__device__ __align__(128) float g_wblk[32 * CH_ELEMS];

// ---------- helpers ----------
__device__ __forceinline__ uint32_t smem_u32(const void* p) {
    uint32_t a;
    asm("{ .reg .u64 t; cvta.to.shared.u64 t, %1; cvt.u32.u64 %0, t; }" : "=r"(a) : "l"(p));
    return a;
}
__device__ __forceinline__ float tf32r(float x) {
    float y; asm("cvt.rna.tf32.f32 %0, %1;" : "=f"(y) : "f"(x));
    return y;
}
__device__ __forceinline__ float tanh_acc(float x) {
    // tanh(x) = 1 - 2/(1 + e^{2x}); ex2/rcp approx ~2^-22 rel err; correct saturation.
    float u = x * 2.885390081777927f;  // 2*log2(e)
    float e; asm("ex2.approx.f32 %0, %1;" : "=f"(e) : "f"(u));
    float r; asm("rcp.approx.f32 %0, %1;" : "=f"(r) : "f"(e + 1.0f));
    return fmaf(-2.0f, r, 1.0f);
}

#define MBINIT(addr, cnt) \
    asm volatile("mbarrier.init.shared.b64 [%0], %1;" :: "r"(addr), "r"(cnt) : "memory")
#define MB_TX(addr, bytes) \
    asm volatile("mbarrier.arrive.expect_tx.shared.b64 _, [%0], %1;" :: "r"(addr), "r"(bytes) : "memory")
#define MB_ARRIVE(addr) \
    asm volatile("mbarrier.arrive.shared.b64 _, [%0];" :: "r"(addr) : "memory")

#define WAITP(addr, par) do { \
    uint32_t _m = (addr), _p = (par), _d; \
    asm volatile("{\n\t.reg .pred p;\n\t" \
        "mbarrier.try_wait.parity.acquire.cta.shared::cta.b64 p, [%1], %2;\n\t" \
        "selp.b32 %0, 1, 0, p;\n\t}" : "=r"(_d) : "r"(_m), "r"(_p) : "memory"); \
    if (!_d) { \
        asm volatile("{\n\t.reg .pred P1;\n\t" \
            "WL_%=:\n\t" \
            "mbarrier.try_wait.parity.acquire.cta.shared::cta.b64 P1, [%0], %1, 0x989680;\n\t" \
            "@P1 bra.uni WD_%=;\n\tbra.uni WL_%=;\n\tWD_%=:\n\t}" \
            :: "r"(_m), "r"(_p) : "memory"); \
    } \
} while (0)

#define WAITPR(addr, par) do { \
    uint32_t _m = (addr), _p = (par), _d; \
    asm volatile("{\n\t.reg .pred p;\n\t" \
        "mbarrier.try_wait.parity.relaxed.cta.shared::cta.b64 p, [%1], %2, 0x989680;\n\t" \
        "selp.b32 %0, 1, 0, p;\n\t}" : "=r"(_d) : "r"(_m), "r"(_p) : "memory"); \
    if (!_d) { \
        asm volatile("{\n\t.reg .pred P1;\n\t" \
            "WL_%=:\n\t" \
            "mbarrier.try_wait.parity.relaxed.cta.shared::cta.b64 P1, [%0], %1, 0x989680;\n\t" \
            "@P1 bra.uni WD_%=;\n\tbra.uni WL_%=;\n\tWD_%=:\n\t}" \
            :: "r"(_m), "r"(_p) : "memory"); \
    } \
} while (0)

// per-half barrier: id 1 for warps 0-7, id 2 for warps 8-15 (256 threads each)
#define BARH(id) asm volatile("bar.sync %0, 256;" :: "r"(id) : "memory")

__device__ __forceinline__ void bulk_g2s(uint32_t dst, const void* src, uint32_t bytes, uint32_t mbar) {
    asm volatile(
        "cp.async.bulk.shared::cluster.global.mbarrier::complete_tx::bytes [%0], [%1], %2, [%3];"
        :: "r"(dst), "l"(src), "r"(bytes), "r"(mbar) : "memory");
}

// mma.sync m16n8k8 tf32 (g=lane>>2, t=lane&3):
// a0=(g,t) a1=(g+8,t) a2=(g,t+4) a3=(g+8,t+4); b0=(t,g) b1=(t+4,g);
// c0=(g,2t) c1=(g,2t+1) c2=(g+8,2t) c3=(g+8,2t+1)
#define MMA8(d, a, bx, by) \
    asm volatile("mma.sync.aligned.m16n8k8.row.col.f32.tf32.tf32.f32 " \
        "{%0,%1,%2,%3}, {%4,%5,%6,%7}, {%8,%9}, {%0,%1,%2,%3};" \
        : "+f"((d)[0]), "+f"((d)[1]), "+f"((d)[2]), "+f"((d)[3]) \
        : "r"((a).x), "r"((a).y), "r"((a).z), "r"((a).w), "r"(bx), "r"(by))

// A-fragment-order store into a 64-row ZH buffer: logical (row 0..63, col 0..255)
__device__ __forceinline__ void zh_store(float* ZH, int row, int col, float v) {
    int tile = ((row >> 4) << 5) + (col >> 3);
    int dl = ((row & 7) << 2) + (col & 3);
    int rr = ((row >> 3) & 1) + (((col >> 2) & 1) << 1);
    ZH[tile * 128 + dl * 4 + rr] = v;
}

// ---------- prep: tf32-round + B-frag uint4-pair k16-slab images ----------
// chunk b = mat*16 + slab: B[k][n] = W[k][n], k in [slab*16,+16), n in [0,256)
// idx e = ((kt*16 + ntp)*32 + lane)*4 + w   (w: bits 0-1, lane: 2-6, ntp: 7-10, kt: 11)
//   k = slab*16 + kt*8 + (lane&3) + 4*(w&1) ; n = (ntp*2 + (w>>1))*8 + (lane>>2)
extern "C" __global__ void __launch_bounds__(256) ode_prep(
    const float* __restrict__ W1, const float* __restrict__ W2) {
    int b = blockIdx.x, mat = b >> 4, slab = b & 15;
    const float* W = mat ? W2 : W1;
    for (int e = threadIdx.x; e < (int)CH_ELEMS; e += 256) {
        int w = e & 3, lane = (e >> 2) & 31, ntp = (e >> 7) & 15, kt = e >> 11;
        int k = slab * 16 + kt * 8 + (lane & 3) + 4 * (w & 1);
        int n = (ntp * 2 + (w >> 1)) * 8 + (lane >> 2);
        g_wblk[b * CH_ELEMS + e] = tf32r(W[k * 256 + n]);
    }
}

// ---------- GEMM pass: D[32x64 per warp] += A(ZH 64-row) @ B(ring), k=256, 16 k16 chunks ----------
__device__ __forceinline__ void gemm_pass(
    float (&d)[2][8][4], const char* smem, uint32_t sb,
    uint32_t zh_off, uint32_t ring_off, uint32_t mb_full, uint32_t mb_empty,
    int mi, int ni, int lane, uint32_t& cs, uint32_t& cp) {
    const uint4* A = (const uint4*)(smem + zh_off);
    for (int kc = 0; kc < 16; kc++) {
        WAITP(sb + mb_full + 16u * cs, cp);
        const uint4* Bk = (const uint4*)(smem + ring_off + cs * CH_BYTES);
#pragma unroll
        for (int kt = 0; kt < 2; kt++) {
            const int ktg = kc * 2 + kt;
            uint4 a[2];
#pragma unroll
            for (int i = 0; i < 2; i++) a[i] = A[((mi * 2 + i) * 32 + ktg) * 32 + lane];
            uint4 b4[4];
#pragma unroll
            for (int jp = 0; jp < 4; jp++) b4[jp] = Bk[(kt * 16 + ni * 4 + jp) * 32 + lane];
#pragma unroll
            for (int i = 0; i < 2; i++)
#pragma unroll
                for (int jp = 0; jp < 4; jp++) {
                    MMA8(d[i][2 * jp + 0], a[i], b4[jp].x, b4[jp].y);
                    MMA8(d[i][2 * jp + 1], a[i], b4[jp].z, b4[jp].w);
                }
        }
        if (lane == 0) MB_ARRIVE(sb + mb_empty + 16u * cs);
        cs++; if (cs == NSTAGE) { cs = 0; cp ^= 1; }
    }
}

// ---------- main persistent kernel ----------
// 128 CTAs x 128 rows, split into two phase-shifted 64-row halves:
// warps 0-7 = half A (rows 0-63), warps 8-15 = half B (rows 64-127), warp 16 = producer.
// Each half: own ZH, own 2-stage ring, own named barrier. Producer staggers ring B
// by 16 chunks (one GEMM phase) so the halves' phases interleave on the SM pipes.
extern "C" __global__ void __launch_bounds__(544, 1) ode_main(
    const float* __restrict__ z0, const float* __restrict__ t_range,
    const float* __restrict__ b1, const float* __restrict__ wt,
    const float* __restrict__ b2, float* __restrict__ out) {
    extern __shared__ char smem[];
    const uint32_t sb = smem_u32(smem);
    const int tid = threadIdx.x, w = tid >> 5, lane = tid & 31;
    const int row0 = blockIdx.x * 128;

    float* sT = (float*)(smem + OFF_T);
    float2* sBW = (float2*)(smem + OFF_BW);
    float* sB2 = (float*)(smem + OFF_B2);

    if (tid == 0) {
        for (int s = 0; s < NSTAGE; s++) {
            MBINIT(sb + 0u + 16u * s, 1);    // ringA full
            MBINIT(sb + 32u + 16u * s, 8);   // ringA empty (8 warps)
            MBINIT(sb + 64u + 16u * s, 1);   // ringB full
            MBINIT(sb + 96u + 16u * s, 8);   // ringB empty
        }
    }
    if (tid < 256) {
        sB2[tid] = b2[tid];
        sBW[tid] = make_float2(b1[tid], wt[tid]);
        if (tid < 25) sT[tid] = t_range[tid];
        // init: z master -> out, tf32 image -> half's ZH (thread owns half a row)
        const int row = tid >> 1, cb = (tid & 1) * 128;
        float* ZH = (float*)(smem + (row < 64 ? OFF_ZH_A : OFF_ZH_B));
        const int rl = row & 63;
        const float4* zp = (const float4*)(z0 + (size_t)(row0 + row) * 256 + cb);
        float4* op = (float4*)(out + (size_t)(row0 + row) * 256 + cb);
#pragma unroll 4
        for (int q = 0; q < 32; q++) {
            float4 v = zp[q];
            op[q] = v;
            int c = cb + q * 4;
            zh_store(ZH, rl, c + 0, tf32r(v.x));
            zh_store(ZH, rl, c + 1, tf32r(v.y));
            zh_store(ZH, rl, c + 2, tf32r(v.z));
            zh_store(ZH, rl, c + 3, tf32r(v.w));
        }
    }
    __syncthreads();

    if (w == 16) {
        // ---- producer: both rings, ring B staggered by 16 chunks (one GEMM phase) ----
        if (lane == 0) {
            uint32_t esA = 0, epA = 1, esB = 0, epB = 1;
            for (int i = 0; i < 816; i++) {
                if (i < 800) {
                    WAITPR(sb + 32u + 16u * esA, epA);
                    MB_TX(sb + 0u + 16u * esA, CH_BYTES);
                    bulk_g2s(sb + OFF_RING_A + esA * CH_BYTES, g_wblk + (i & 31) * CH_ELEMS,
                             CH_BYTES, sb + 0u + 16u * esA);
                    esA++; if (esA == NSTAGE) { esA = 0; epA ^= 1; }
                }
                int j = i - 16;
                if (j >= 0) {
                    WAITPR(sb + 96u + 16u * esB, epB);
                    MB_TX(sb + 64u + 16u * esB, CH_BYTES);
                    bulk_g2s(sb + OFF_RING_B + esB * CH_BYTES, g_wblk + (j & 31) * CH_ELEMS,
                             CH_BYTES, sb + 64u + 16u * esB);
                    esB++; if (esB == NSTAGE) { esB = 0; epB ^= 1; }
                }
            }
        }
        return;
    }

    // ---- compute warps ----
    const int half = w >> 3, wl = w & 7;
    const int mi = wl >> 2, ni = wl & 3;  // warp tile: local rows [mi*32,+32), cols [ni*64,+64)
    const int gid = lane >> 2, tig = lane & 3;
    const float dt = sT[1] - sT[0];
    const uint32_t zh_off = half ? OFF_ZH_B : OFF_ZH_A;
    const uint32_t ring_off = half ? OFF_RING_B : OFF_RING_A;
    const uint32_t mb_full = half ? 64u : 0u;
    const uint32_t mb_empty = half ? 96u : 32u;
    const int bar_id = 1 + half;
    const int grow0 = row0 + half * 64;  // this half's first global row
    float* ZH = (float*)(smem + zh_off);
    uint32_t cs = 0, cp = 0;
    float d[2][8][4];

    for (int s = 0; s < 25; s++) {
        const float t = sT[s];
        // ---- GEMM1: D = z @ W1 ----
#pragma unroll
        for (int i = 0; i < 2; i++)
#pragma unroll
            for (int j = 0; j < 8; j++)
#pragma unroll
                for (int r = 0; r < 4; r++) d[i][j][r] = 0.0f;
        gemm_pass(d, smem, sb, zh_off, ring_off, mb_full, mb_empty, mi, ni, lane, cs, cp);
        BARH(bar_id);  // half done reading ZH (z)
        // ---- h = tanh(D + b1 + t*wt) -> ZH (tf32, A-frag order) ----
#pragma unroll
        for (int i = 0; i < 2; i++)
#pragma unroll
            for (int j = 0; j < 8; j++)
#pragma unroll
                for (int r = 0; r < 4; r++) {
                    int row = mi * 32 + i * 16 + gid + ((r & 2) ? 8 : 0);
                    int col = ni * 64 + j * 8 + 2 * tig + (r & 1);
                    float2 bw = sBW[col];
                    float x = d[i][j][r] + bw.x + t * bw.y;
                    zh_store(ZH, row, col, tf32r(tanh_acc(x)));
                }
        BARH(bar_id);  // h fully written
        // ---- GEMM2: D = h @ W2 ----
#pragma unroll
        for (int i = 0; i < 2; i++)
#pragma unroll
            for (int j = 0; j < 8; j++)
#pragma unroll
                for (int r = 0; r < 4; r++) d[i][j][r] = 0.0f;
        gemm_pass(d, smem, sb, zh_off, ring_off, mb_full, mb_empty, mi, ni, lane, cs, cp);
        BARH(bar_id);  // half done reading ZH (h)
        // ---- z update: z += dt*(D + b2); fp32 master in out, tf32 image -> ZH ----
#pragma unroll
        for (int i = 0; i < 2; i++)
#pragma unroll
            for (int j = 0; j < 8; j++)
#pragma unroll
                for (int rp = 0; rp < 2; rp++) {
                    int row = mi * 32 + i * 16 + gid + rp * 8;
                    int col = ni * 64 + j * 8 + 2 * tig;
                    size_t g = (size_t)(grow0 + row) * 256 + col;
                    float2 zo = *(const float2*)(out + g);
                    float zn0 = fmaf(dt, d[i][j][2 * rp + 0] + sB2[col + 0], zo.x);
                    float zn1 = fmaf(dt, d[i][j][2 * rp + 1] + sB2[col + 1], zo.y);
                    *(float2*)(out + g) = make_float2(zn0, zn1);
                    zh_store(ZH, row, col + 0, tf32r(zn0));
                    zh_store(ZH, row, col + 1, tf32r(zn1));
                }
        BARH(bar_id);  // z image ready for next step's GEMM1
    }
}

extern "C" void kernel_launch(void* const* d_in, const int* in_sizes, int n_in,
                              void* d_out, int out_size) {
    const float* z0 = (const float*)d_in[0];
    const float* t_range = (const float*)d_in[1];
    const float* W1 = (const float*)d_in[2];
    const float* b1 = (const float*)d_in[3];
    const float* wt = (const float*)d_in[4];
    const float* W2 = (const float*)d_in[5];
    const float* b2 = (const float*)d_in[6];
    float* out = (float*)d_out;

    cudaFuncSetAttribute(ode_main, cudaFuncAttributeMaxDynamicSharedMemorySize, DYN_SMEM);
    ode_prep<<<32, 256>>>(W1, W2);
    ode_main<<<128, 544, DYN_SMEM>>>(z0, t_range, b1, wt, b2, out);
}

// round 11
// speedup vs baseline: 1.6755x; 1.6755x over previous
#include <cuda_runtime.h>
#include <stdint.h>

#define NSTAGE 8
#define CH_U2 2048u      // one 16KB chunk: [2 kt][32 nt][32 lane] uint2 (fp16 b-frags, k32 slab)
#define CH_BYTES 16384u

// dynamic smem layout (bytes)
// mbars: full[8] @ 0..128, empty[8] @ 128..256
#define OFF_T 256u                               // t_range 25 f32
#define OFF_BW 384u                              // float2 (b1, wt)[256] -> 2048B
#define OFF_B2 2432u                             // f32 b2[256] -> 1024B
#define OFF_ZH 3584u                             // 128x256 fp16 in A-frag order = 65536B
#define OFF_RING (OFF_ZH + 65536u)               // 69120
#define DYN_SMEM (OFF_RING + NSTAGE * CH_BYTES)  // 200192

// prep output: 16 chunks (W1 k32-slabs 0-7, W2 k32-slabs 8-15) of 16KB fp16 b-frag images
__device__ __align__(128) uint2 g_wblk[16 * CH_U2];

// ---------- helpers ----------
__device__ __forceinline__ uint32_t smem_u32(const void* p) {
    uint32_t a;
    asm("{ .reg .u64 t; cvta.to.shared.u64 t, %1; cvt.u32.u64 %0, t; }" : "=r"(a) : "l"(p));
    return a;
}
// pack two f32 -> f16x2 (lo = first arg, hi = second), round-to-nearest
__device__ __forceinline__ uint32_t pack_h2(float lo, float hi) {
    uint32_t r;
    asm("cvt.rn.f16x2.f32 %0, %1, %2;" : "=r"(r) : "f"(hi), "f"(lo));
    return r;
}
__device__ __forceinline__ float tanh_acc(float x) {
    // tanh(x) = 1 - 2/(1 + e^{2x}); ex2/rcp approx ~2^-22 rel err; correct saturation.
    float u = x * 2.885390081777927f;  // 2*log2(e)
    float e; asm("ex2.approx.f32 %0, %1;" : "=f"(e) : "f"(u));
    float r; asm("rcp.approx.f32 %0, %1;" : "=f"(r) : "f"(e + 1.0f));
    return fmaf(-2.0f, r, 1.0f);
}

#define MBINIT(addr, cnt) \
    asm volatile("mbarrier.init.shared.b64 [%0], %1;" :: "r"(addr), "r"(cnt) : "memory")
#define MB_TX(addr, bytes) \
    asm volatile("mbarrier.arrive.expect_tx.shared.b64 _, [%0], %1;" :: "r"(addr), "r"(bytes) : "memory")
#define MB_ARRIVE(addr) \
    asm volatile("mbarrier.arrive.shared.b64 _, [%0];" :: "r"(addr) : "memory")

#define WAITP(addr, par) do { \
    uint32_t _m = (addr), _p = (par), _d; \
    asm volatile("{\n\t.reg .pred p;\n\t" \
        "mbarrier.try_wait.parity.acquire.cta.shared::cta.b64 p, [%1], %2;\n\t" \
        "selp.b32 %0, 1, 0, p;\n\t}" : "=r"(_d) : "r"(_m), "r"(_p) : "memory"); \
    if (!_d) { \
        asm volatile("{\n\t.reg .pred P1;\n\t" \
            "WL_%=:\n\t" \
            "mbarrier.try_wait.parity.acquire.cta.shared::cta.b64 P1, [%0], %1, 0x989680;\n\t" \
            "@P1 bra.uni WD_%=;\n\tbra.uni WL_%=;\n\tWD_%=:\n\t}" \
            :: "r"(_m), "r"(_p) : "memory"); \
    } \
} while (0)

#define WAITPR(addr, par) do { \
    uint32_t _m = (addr), _p = (par), _d; \
    asm volatile("{\n\t.reg .pred p;\n\t" \
        "mbarrier.try_wait.parity.relaxed.cta.shared::cta.b64 p, [%1], %2, 0x989680;\n\t" \
        "selp.b32 %0, 1, 0, p;\n\t}" : "=r"(_d) : "r"(_m), "r"(_p) : "memory"); \
    if (!_d) { \
        asm volatile("{\n\t.reg .pred P1;\n\t" \
            "WL_%=:\n\t" \
            "mbarrier.try_wait.parity.relaxed.cta.shared::cta.b64 P1, [%0], %1, 0x989680;\n\t" \
            "@P1 bra.uni WD_%=;\n\tbra.uni WL_%=;\n\tWD_%=:\n\t}" \
            :: "r"(_m), "r"(_p) : "memory"); \
    } \
} while (0)

#define BAR1() asm volatile("bar.sync 1, 512;" ::: "memory")

__device__ __forceinline__ void bulk_g2s(uint32_t dst, const void* src, uint32_t bytes, uint32_t mbar) {
    asm volatile(
        "cp.async.bulk.shared::cluster.global.mbarrier::complete_tx::bytes [%0], [%1], %2, [%3];"
        :: "r"(dst), "l"(src), "r"(bytes), "r"(mbar) : "memory");
}

// mma.sync m16n8k16 f16->f32 (g=lane>>2, t=lane&3):
// a0=(g,2t:2t+1) a1=(g+8,2t:2t+1) a2=(g,2t+8:2t+9) a3=(g+8,2t+8:2t+9)  [lo = even k]
// b0=(2t:2t+1, g) b1=(2t+8:2t+9, g)                                     [lo = even k]
// c0=(g,2t) c1=(g,2t+1) c2=(g+8,2t) c3=(g+8,2t+1)
#define MMA16(d, a, bx, by) \
    asm volatile("mma.sync.aligned.m16n8k16.row.col.f32.f16.f16.f32 " \
        "{%0,%1,%2,%3}, {%4,%5,%6,%7}, {%8,%9}, {%0,%1,%2,%3};" \
        : "+f"((d)[0]), "+f"((d)[1]), "+f"((d)[2]), "+f"((d)[3]) \
        : "r"((a).x), "r"((a).y), "r"((a).z), "r"((a).w), "r"(bx), "r"(by))

// A-fragment-order store of a packed col-pair into ZH: (row 0..127, colpair 0..127)
// tile (mtile16, ktile16) holds 32 lanes x uint4 {a0,a1,a2,a3}; uint32 index:
__device__ __forceinline__ void zh_store_pair(uint32_t* ZH, int row, int cp, uint32_t v) {
    int tile = ((row >> 4) << 4) + (cp >> 3);
    int lane = ((row & 7) << 2) + (cp & 3);
    int comp = ((row >> 3) & 1) + (((cp >> 2) & 1) << 1);
    ZH[tile * 128 + lane * 4 + comp] = v;
}

// ---------- prep: fp16-round + B-frag k32-slab images ----------
// chunk c = mat*8 + slab: B[k][n] = W[k][n], k in [slab*32,+32), n in [0,256)
// uint2 at ((kt*32 + nt)*32 + lane): b0 = {W[kb+2t][n], W[kb+2t+1][n]},
// b1 = {W[kb+2t+8][n], W[kb+2t+9][n]}, kb = slab*32 + kt*16, n = nt*8 + g
extern "C" __global__ void __launch_bounds__(256) ode_prep(
    const float* __restrict__ W1, const float* __restrict__ W2) {
    int c = blockIdx.x, mat = c >> 3, slab = c & 7;
    const float* W = mat ? W2 : W1;
    for (int e = threadIdx.x; e < (int)CH_U2; e += 256) {
        int lane = e & 31, nt = (e >> 5) & 31, kt = e >> 10;
        int g = lane >> 2, t = lane & 3;
        int kb = slab * 32 + kt * 16, n = nt * 8 + g;
        uint2 v;
        v.x = pack_h2(W[(kb + 2 * t) * 256 + n], W[(kb + 2 * t + 1) * 256 + n]);
        v.y = pack_h2(W[(kb + 2 * t + 8) * 256 + n], W[(kb + 2 * t + 9) * 256 + n]);
        g_wblk[c * CH_U2 + e] = v;
    }
}

// ---------- GEMM pass: D[32x64 per warp] += A(ZH) @ B(ring), k=256 over 8 k32 chunks ----------
__device__ __forceinline__ void gemm_pass(
    float (&d)[2][8][4], const char* smem, uint32_t sb,
    int mi, int ni, int lane, uint32_t& cs, uint32_t& cp) {
    const uint4* A = (const uint4*)(smem + OFF_ZH);
    for (int kc = 0; kc < 8; kc++) {
        WAITP(sb + 16u * cs, cp);
        const uint2* Bk = (const uint2*)(smem + OFF_RING + cs * CH_BYTES);
#pragma unroll
        for (int kt = 0; kt < 2; kt++) {
            const int ktile = kc * 2 + kt;
            uint4 a[2];
#pragma unroll
            for (int i = 0; i < 2; i++) a[i] = A[(((mi * 2 + i) << 4) + ktile) * 32 + lane];
            uint2 b[8];
#pragma unroll
            for (int j = 0; j < 8; j++) b[j] = Bk[(kt * 32 + ni * 8 + j) * 32 + lane];
#pragma unroll
            for (int i = 0; i < 2; i++)
#pragma unroll
                for (int j = 0; j < 8; j++) MMA16(d[i][j], a[i], b[j].x, b[j].y);
        }
        if (lane == 0) MB_ARRIVE(sb + 128u + 16u * cs);
        cs++; if (cs == NSTAGE) { cs = 0; cp ^= 1; }
    }
}

// ---------- main persistent kernel ----------
// 128 CTAs x 128 rows; warps 0-15 compute (4x4 grid of 32x64 tiles), warp 16 = producer.
extern "C" __global__ void __launch_bounds__(544, 1) ode_main(
    const float* __restrict__ z0, const float* __restrict__ t_range,
    const float* __restrict__ b1, const float* __restrict__ wt,
    const float* __restrict__ b2, float* __restrict__ out) {
    extern __shared__ char smem[];
    const uint32_t sb = smem_u32(smem);
    const int tid = threadIdx.x, w = tid >> 5, lane = tid & 31;
    const int row0 = blockIdx.x * 128;

    uint32_t* ZH = (uint32_t*)(smem + OFF_ZH);
    float* sT = (float*)(smem + OFF_T);
    float2* sBW = (float2*)(smem + OFF_BW);
    float* sB2 = (float*)(smem + OFF_B2);

    if (tid == 0) {
        for (int s = 0; s < NSTAGE; s++) {
            MBINIT(sb + 16u * s, 1);          // full: producer MB_TX(1 arrive) + bulk bytes
            MBINIT(sb + 128u + 16u * s, 16);  // empty: one arrive per compute warp
        }
    }
    if (tid < 256) {
        sB2[tid] = b2[tid];
        sBW[tid] = make_float2(b1[tid], wt[tid]);
        if (tid < 25) sT[tid] = t_range[tid];
        // init: z master -> out, fp16 image -> ZH (thread owns half a row = 64 col-pairs)
        const int row = tid >> 1, cb = (tid & 1) * 128;
        const float4* zp = (const float4*)(z0 + (size_t)(row0 + row) * 256 + cb);
        float4* op = (float4*)(out + (size_t)(row0 + row) * 256 + cb);
#pragma unroll 4
        for (int q = 0; q < 32; q++) {
            float4 v = zp[q];
            op[q] = v;
            int cp0 = (cb >> 1) + 2 * q;
            zh_store_pair(ZH, row, cp0 + 0, pack_h2(v.x, v.y));
            zh_store_pair(ZH, row, cp0 + 1, pack_h2(v.z, v.w));
        }
    }
    __syncthreads();

    if (w == 16) {
        // ---- producer: 25 steps x 16 chunks (W1 slabs 0-7 then W2 slabs 8-15) ----
        if (lane == 0) {
            uint32_t es = 0, ep = 1;
            for (int i = 0; i < 400; i++) {
                WAITPR(sb + 128u + 16u * es, ep);
                MB_TX(sb + 16u * es, CH_BYTES);
                bulk_g2s(sb + OFF_RING + es * CH_BYTES, g_wblk + (i & 15) * CH_U2,
                         CH_BYTES, sb + 16u * es);
                es++; if (es == NSTAGE) { es = 0; ep ^= 1; }
            }
        }
        return;
    }

    // ---- compute warps ----
    const int mi = w >> 2, ni = w & 3;  // warp tile: rows [mi*32,+32), cols [ni*64,+64)
    const int gid = lane >> 2, tig = lane & 3;
    const float dt = sT[1] - sT[0];
    uint32_t cs = 0, cp = 0;
    float d[2][8][4];

    for (int s = 0; s < 25; s++) {
        const float t = sT[s];
        // ---- GEMM1: D = z @ W1 ----
#pragma unroll
        for (int i = 0; i < 2; i++)
#pragma unroll
            for (int j = 0; j < 8; j++)
#pragma unroll
                for (int r = 0; r < 4; r++) d[i][j][r] = 0.0f;
        gemm_pass(d, smem, sb, mi, ni, lane, cs, cp);
        BAR1();  // all warps done reading ZH (z)
        // ---- h = tanh(D + b1 + t*wt) -> ZH (fp16 pairs; col is GEMM2's k) ----
#pragma unroll
        for (int i = 0; i < 2; i++)
#pragma unroll
            for (int j = 0; j < 8; j++) {
                const int col = ni * 64 + j * 8 + 2 * tig;
                const int cpair = ni * 32 + j * 4 + tig;
                const float2 bw0 = sBW[col], bw1 = sBW[col + 1];
                const int row = mi * 32 + i * 16 + gid;
                float h0 = tanh_acc(d[i][j][0] + bw0.x + t * bw0.y);
                float h1 = tanh_acc(d[i][j][1] + bw1.x + t * bw1.y);
                zh_store_pair(ZH, row, cpair, pack_h2(h0, h1));
                float h2 = tanh_acc(d[i][j][2] + bw0.x + t * bw0.y);
                float h3 = tanh_acc(d[i][j][3] + bw1.x + t * bw1.y);
                zh_store_pair(ZH, row + 8, cpair, pack_h2(h2, h3));
            }
        BAR1();  // h fully written
        // ---- GEMM2: D = h @ W2 ----
#pragma unroll
        for (int i = 0; i < 2; i++)
#pragma unroll
            for (int j = 0; j < 8; j++)
#pragma unroll
                for (int r = 0; r < 4; r++) d[i][j][r] = 0.0f;
        gemm_pass(d, smem, sb, mi, ni, lane, cs, cp);
        BAR1();  // all warps done reading ZH (h)
        // ---- z update: z += dt*(D + b2); fp32 master in out, fp16 image -> ZH ----
#pragma unroll
        for (int i = 0; i < 2; i++)
#pragma unroll
            for (int j = 0; j < 8; j++) {
                const int col = ni * 64 + j * 8 + 2 * tig;
                const int cpair = ni * 32 + j * 4 + tig;
#pragma unroll
                for (int rp = 0; rp < 2; rp++) {
                    int row = mi * 32 + i * 16 + gid + rp * 8;
                    size_t g = (size_t)(row0 + row) * 256 + col;
                    float2 zo = *(const float2*)(out + g);
                    float zn0 = fmaf(dt, d[i][j][2 * rp + 0] + sB2[col + 0], zo.x);
                    float zn1 = fmaf(dt, d[i][j][2 * rp + 1] + sB2[col + 1], zo.y);
                    *(float2*)(out + g) = make_float2(zn0, zn1);
                    zh_store_pair(ZH, row, cpair, pack_h2(zn0, zn1));
                }
            }
        BAR1();  // z image ready for next step's GEMM1
    }
}

extern "C" void kernel_launch(void* const* d_in, const int* in_sizes, int n_in,
                              void* d_out, int out_size) {
    const float* z0 = (const float*)d_in[0];
    const float* t_range = (const float*)d_in[1];
    const float* W1 = (const float*)d_in[2];
    const float* b1 = (const float*)d_in[3];
    const float* wt = (const float*)d_in[4];
    const float* W2 = (const float*)d_in[5];
    const float* b2 = (const float*)d_in[6];
    float* out = (float*)d_out;

    cudaFuncSetAttribute(ode_main, cudaFuncAttributeMaxDynamicSharedMemorySize, DYN_SMEM);
    ode_prep<<<16, 256>>>(W1, W2);
    ode_main<<<128, 544, DYN_SMEM>>>(z0, t_range, b1, wt, b2, out);
}

// round 12
// speedup vs baseline: 1.6974x; 1.0131x over previous
#include <cuda_runtime.h>
#include <stdint.h>

#define NSTAGE 4
#define CH_U2 2048u      // one 16KB chunk: [2 kt][32 nt][32 lane] uint2 (fp16 b-frags, k32 slab)
#define CH_BYTES 16384u

// dynamic smem layout (bytes)
// mbars: full[4] @ 0..64, empty[4] @ 64..128
#define OFF_T 128u                               // t_range 25 f32
#define OFF_BW 384u                              // float2 (b1, wt)[256] -> 2048B
#define OFF_B2 2432u                             // f32 b2[256] -> 1024B
#define OFF_Z 3584u                              // 128x256 fp16 A-frag order = 65536B
#define OFF_H (OFF_Z + 65536u)                   // 69120
#define OFF_RING (OFF_H + 65536u)                // 134656
#define DYN_SMEM (OFF_RING + NSTAGE * CH_BYTES)  // 200192

// prep output: 16 chunks (W1 k32-slabs 0-7, W2 k32-slabs 8-15) of 16KB fp16 b-frag images
__device__ __align__(128) uint2 g_wblk[16 * CH_U2];

// ---------- helpers ----------
__device__ __forceinline__ uint32_t smem_u32(const void* p) {
    uint32_t a;
    asm("{ .reg .u64 t; cvta.to.shared.u64 t, %1; cvt.u32.u64 %0, t; }" : "=r"(a) : "l"(p));
    return a;
}
// pack two f32 -> f16x2 (lo = first arg, hi = second), round-to-nearest
__device__ __forceinline__ uint32_t pack_h2(float lo, float hi) {
    uint32_t r;
    asm("cvt.rn.f16x2.f32 %0, %1, %2;" : "=r"(r) : "f"(hi), "f"(lo));
    return r;
}
__device__ __forceinline__ float tanh_acc(float x) {
    // tanh(x) = 1 - 2/(1 + e^{2x}); ex2/rcp approx ~2^-22 rel err; correct saturation.
    float u = x * 2.885390081777927f;  // 2*log2(e)
    float e; asm("ex2.approx.f32 %0, %1;" : "=f"(e) : "f"(u));
    float r; asm("rcp.approx.f32 %0, %1;" : "=f"(r) : "f"(e + 1.0f));
    return fmaf(-2.0f, r, 1.0f);
}

#define MBINIT(addr, cnt) \
    asm volatile("mbarrier.init.shared.b64 [%0], %1;" :: "r"(addr), "r"(cnt) : "memory")
#define MB_TX(addr, bytes) \
    asm volatile("mbarrier.arrive.expect_tx.shared.b64 _, [%0], %1;" :: "r"(addr), "r"(bytes) : "memory")
#define MB_ARRIVE(addr) \
    asm volatile("mbarrier.arrive.shared.b64 _, [%0];" :: "r"(addr) : "memory")

#define WAITP(addr, par) do { \
    uint32_t _m = (addr), _p = (par), _d; \
    asm volatile("{\n\t.reg .pred p;\n\t" \
        "mbarrier.try_wait.parity.acquire.cta.shared::cta.b64 p, [%1], %2;\n\t" \
        "selp.b32 %0, 1, 0, p;\n\t}" : "=r"(_d) : "r"(_m), "r"(_p) : "memory"); \
    if (!_d) { \
        asm volatile("{\n\t.reg .pred P1;\n\t" \
            "WL_%=:\n\t" \
            "mbarrier.try_wait.parity.acquire.cta.shared::cta.b64 P1, [%0], %1, 0x989680;\n\t" \
            "@P1 bra.uni WD_%=;\n\tbra.uni WL_%=;\n\tWD_%=:\n\t}" \
            :: "r"(_m), "r"(_p) : "memory"); \
    } \
} while (0)

#define WAITPR(addr, par) do { \
    uint32_t _m = (addr), _p = (par), _d; \
    asm volatile("{\n\t.reg .pred p;\n\t" \
        "mbarrier.try_wait.parity.relaxed.cta.shared::cta.b64 p, [%1], %2, 0x989680;\n\t" \
        "selp.b32 %0, 1, 0, p;\n\t}" : "=r"(_d) : "r"(_m), "r"(_p) : "memory"); \
    if (!_d) { \
        asm volatile("{\n\t.reg .pred P1;\n\t" \
            "WL_%=:\n\t" \
            "mbarrier.try_wait.parity.relaxed.cta.shared::cta.b64 P1, [%0], %1, 0x989680;\n\t" \
            "@P1 bra.uni WD_%=;\n\tbra.uni WL_%=;\n\tWD_%=:\n\t}" \
            :: "r"(_m), "r"(_p) : "memory"); \
    } \
} while (0)

#define BAR1() asm volatile("bar.sync 1, 512;" ::: "memory")

__device__ __forceinline__ void bulk_g2s(uint32_t dst, const void* src, uint32_t bytes, uint32_t mbar) {
    asm volatile(
        "cp.async.bulk.shared::cluster.global.mbarrier::complete_tx::bytes [%0], [%1], %2, [%3];"
        :: "r"(dst), "l"(src), "r"(bytes), "r"(mbar) : "memory");
}

// mma.sync m16n8k16 f16->f32 (g=lane>>2, t=lane&3):
// a0=(g,2t:2t+1) a1=(g+8,2t:2t+1) a2=(g,2t+8:2t+9) a3=(g+8,2t+8:2t+9)  [lo = even k]
// b0=(2t:2t+1, g) b1=(2t+8:2t+9, g)                                     [lo = even k]
// c0=(g,2t) c1=(g,2t+1) c2=(g+8,2t) c3=(g+8,2t+1)
#define MMA16(d, a, bx, by) \
    asm volatile("mma.sync.aligned.m16n8k16.row.col.f32.f16.f16.f32 " \
        "{%0,%1,%2,%3}, {%4,%5,%6,%7}, {%8,%9}, {%0,%1,%2,%3};" \
        : "+f"((d)[0]), "+f"((d)[1]), "+f"((d)[2]), "+f"((d)[3]) \
        : "r"((a).x), "r"((a).y), "r"((a).z), "r"((a).w), "r"(bx), "r"(by))

// A-fragment-order store of a packed col-pair: (row 0..127, colpair 0..127)
__device__ __forceinline__ void zh_store_pair(uint32_t* ZB, int row, int cp, uint32_t v) {
    int tile = ((row >> 4) << 4) + (cp >> 3);
    int lane = ((row & 7) << 2) + (cp & 3);
    int comp = ((row >> 3) & 1) + (((cp >> 2) & 1) << 1);
    ZB[tile * 128 + lane * 4 + comp] = v;
}

// ---------- prep: fp16-round + B-frag k32-slab images ----------
// chunk c = mat*8 + slab: B[k][n] = W[k][n], k in [slab*32,+32), n in [0,256)
// uint2 at ((kt*32 + nt)*32 + lane): b0 = {W[kb+2t][n], W[kb+2t+1][n]},
// b1 = {W[kb+2t+8][n], W[kb+2t+9][n]}, kb = slab*32 + kt*16, n = nt*8 + g
extern "C" __global__ void __launch_bounds__(256) ode_prep(
    const float* __restrict__ W1, const float* __restrict__ W2) {
    int c = blockIdx.x, mat = c >> 3, slab = c & 7;
    const float* W = mat ? W2 : W1;
    for (int e = threadIdx.x; e < (int)CH_U2; e += 256) {
        int lane = e & 31, nt = (e >> 5) & 31, kt = e >> 10;
        int g = lane >> 2, t = lane & 3;
        int kb = slab * 32 + kt * 16, n = nt * 8 + g;
        uint2 v;
        v.x = pack_h2(W[(kb + 2 * t) * 256 + n], W[(kb + 2 * t + 1) * 256 + n]);
        v.y = pack_h2(W[(kb + 2 * t + 8) * 256 + n], W[(kb + 2 * t + 9) * 256 + n]);
        g_wblk[c * CH_U2 + e] = v;
    }
}

// ---------- GEMM pass: D[32x64 per warp] += A(src buf) @ B(ring), k=256 over 8 k32 chunks ----------
__device__ __forceinline__ void gemm_pass(
    float (&d)[2][8][4], const char* smem, uint32_t sb, uint32_t a_off,
    int mi, int ni, int lane, uint32_t& cs, uint32_t& cp) {
    const uint4* A = (const uint4*)(smem + a_off);
    for (int kc = 0; kc < 8; kc++) {
        WAITP(sb + 16u * cs, cp);
        const uint2* Bk = (const uint2*)(smem + OFF_RING + cs * CH_BYTES);
#pragma unroll
        for (int kt = 0; kt < 2; kt++) {
            const int ktile = kc * 2 + kt;
            uint4 a[2];
#pragma unroll
            for (int i = 0; i < 2; i++) a[i] = A[(((mi * 2 + i) << 4) + ktile) * 32 + lane];
            uint2 b[8];
#pragma unroll
            for (int j = 0; j < 8; j++) b[j] = Bk[(kt * 32 + ni * 8 + j) * 32 + lane];
#pragma unroll
            for (int i = 0; i < 2; i++)
#pragma unroll
                for (int j = 0; j < 8; j++) MMA16(d[i][j], a[i], b[j].x, b[j].y);
        }
        if (lane == 0) MB_ARRIVE(sb + 64u + 16u * cs);
        cs++; if (cs == NSTAGE) { cs = 0; cp ^= 1; }
    }
}

// ---------- main persistent kernel ----------
// 128 CTAs x 128 rows; warps 0-15 compute (4x4 grid of 32x64 tiles), warp 16 = producer.
// Separate Z and H buffers -> only 2 barriers/step (H-ready, Z-ready); tanh and zupd
// run immediately after each warp's own GEMM, overlapping other warps' MMA via skew.
extern "C" __global__ void __launch_bounds__(544, 1) ode_main(
    const float* __restrict__ z0, const float* __restrict__ t_range,
    const float* __restrict__ b1, const float* __restrict__ wt,
    const float* __restrict__ b2, float* __restrict__ out) {
    extern __shared__ char smem[];
    const uint32_t sb = smem_u32(smem);
    const int tid = threadIdx.x, w = tid >> 5, lane = tid & 31;
    const int row0 = blockIdx.x * 128;

    uint32_t* ZB = (uint32_t*)(smem + OFF_Z);
    uint32_t* HB = (uint32_t*)(smem + OFF_H);
    float* sT = (float*)(smem + OFF_T);
    float2* sBW = (float2*)(smem + OFF_BW);
    float* sB2 = (float*)(smem + OFF_B2);

    if (tid == 0) {
        for (int s = 0; s < NSTAGE; s++) {
            MBINIT(sb + 16u * s, 1);         // full: producer MB_TX(1 arrive) + bulk bytes
            MBINIT(sb + 64u + 16u * s, 16);  // empty: one arrive per compute warp
        }
    }
    if (tid < 256) {
        sB2[tid] = b2[tid];
        sBW[tid] = make_float2(b1[tid], wt[tid]);
        if (tid < 25) sT[tid] = t_range[tid];
        // init: z master -> out, fp16 image -> Z (thread owns half a row = 64 col-pairs)
        const int row = tid >> 1, cb = (tid & 1) * 128;
        const float4* zp = (const float4*)(z0 + (size_t)(row0 + row) * 256 + cb);
        float4* op = (float4*)(out + (size_t)(row0 + row) * 256 + cb);
#pragma unroll 4
        for (int q = 0; q < 32; q++) {
            float4 v = zp[q];
            op[q] = v;
            int cp0 = (cb >> 1) + 2 * q;
            zh_store_pair(ZB, row, cp0 + 0, pack_h2(v.x, v.y));
            zh_store_pair(ZB, row, cp0 + 1, pack_h2(v.z, v.w));
        }
    }
    __syncthreads();

    if (w == 16) {
        // ---- producer: 25 steps x 16 chunks (W1 slabs 0-7 then W2 slabs 8-15) ----
        if (lane == 0) {
            uint32_t es = 0, ep = 1;
            for (int i = 0; i < 400; i++) {
                WAITPR(sb + 64u + 16u * es, ep);
                MB_TX(sb + 16u * es, CH_BYTES);
                bulk_g2s(sb + OFF_RING + es * CH_BYTES, g_wblk + (i & 15) * CH_U2,
                         CH_BYTES, sb + 16u * es);
                es++; if (es == NSTAGE) { es = 0; ep ^= 1; }
            }
        }
        return;
    }

    // ---- compute warps ----
    const int mi = w >> 2, ni = w & 3;  // warp tile: rows [mi*32,+32), cols [ni*64,+64)
    const int gid = lane >> 2, tig = lane & 3;
    const float dt = sT[1] - sT[0];
    uint32_t cs = 0, cp = 0;
    float d[2][8][4];

    for (int s = 0; s < 25; s++) {
        const float t = sT[s];
        // ---- GEMM1: D = z @ W1 (reads Z) ----
#pragma unroll
        for (int i = 0; i < 2; i++)
#pragma unroll
            for (int j = 0; j < 8; j++)
#pragma unroll
                for (int r = 0; r < 4; r++) d[i][j][r] = 0.0f;
        gemm_pass(d, smem, sb, OFF_Z, mi, ni, lane, cs, cp);
        // ---- h = tanh(D + b1 + t*wt) -> H (no barrier: H != Z) ----
#pragma unroll
        for (int i = 0; i < 2; i++)
#pragma unroll
            for (int j = 0; j < 8; j++) {
                const int col = ni * 64 + j * 8 + 2 * tig;
                const int cpair = ni * 32 + j * 4 + tig;
                const float2 bw0 = sBW[col], bw1 = sBW[col + 1];
                const int row = mi * 32 + i * 16 + gid;
                float h0 = tanh_acc(d[i][j][0] + bw0.x + t * bw0.y);
                float h1 = tanh_acc(d[i][j][1] + bw1.x + t * bw1.y);
                zh_store_pair(HB, row, cpair, pack_h2(h0, h1));
                float h2 = tanh_acc(d[i][j][2] + bw0.x + t * bw0.y);
                float h3 = tanh_acc(d[i][j][3] + bw1.x + t * bw1.y);
                zh_store_pair(HB, row + 8, cpair, pack_h2(h2, h3));
            }
        BAR1();  // H fully written (also implies all Z reads done)
        // ---- GEMM2: D = h @ W2 (reads H) ----
#pragma unroll
        for (int i = 0; i < 2; i++)
#pragma unroll
            for (int j = 0; j < 8; j++)
#pragma unroll
                for (int r = 0; r < 4; r++) d[i][j][r] = 0.0f;
        gemm_pass(d, smem, sb, OFF_H, mi, ni, lane, cs, cp);
        // ---- z update: z += dt*(D + b2) -> out + Z (no barrier: Z != H) ----
#pragma unroll
        for (int i = 0; i < 2; i++)
#pragma unroll
            for (int j = 0; j < 8; j++) {
                const int col = ni * 64 + j * 8 + 2 * tig;
                const int cpair = ni * 32 + j * 4 + tig;
#pragma unroll
                for (int rp = 0; rp < 2; rp++) {
                    int row = mi * 32 + i * 16 + gid + rp * 8;
                    size_t g = (size_t)(row0 + row) * 256 + col;
                    float2 zo = *(const float2*)(out + g);
                    float zn0 = fmaf(dt, d[i][j][2 * rp + 0] + sB2[col + 0], zo.x);
                    float zn1 = fmaf(dt, d[i][j][2 * rp + 1] + sB2[col + 1], zo.y);
                    *(float2*)(out + g) = make_float2(zn0, zn1);
                    zh_store_pair(ZB, row, cpair, pack_h2(zn0, zn1));
                }
            }
        BAR1();  // Z fully written (also implies all H reads done)
    }
}

extern "C" void kernel_launch(void* const* d_in, const int* in_sizes, int n_in,
                              void* d_out, int out_size) {
    const float* z0 = (const float*)d_in[0];
    const float* t_range = (const float*)d_in[1];
    const float* W1 = (const float*)d_in[2];
    const float* b1 = (const float*)d_in[3];
    const float* wt = (const float*)d_in[4];
    const float* W2 = (const float*)d_in[5];
    const float* b2 = (const float*)d_in[6];
    float* out = (float*)d_out;

    cudaFuncSetAttribute(ode_main, cudaFuncAttributeMaxDynamicSharedMemorySize, DYN_SMEM);
    ode_prep<<<16, 256>>>(W1, W2);
    ode_main<<<128, 544, DYN_SMEM>>>(z0, t_range, b1, wt, b2, out);
}

// round 13
// speedup vs baseline: 1.8684x; 1.1008x over previous
#include <cuda_runtime.h>
#include <stdint.h>

#define NSTAGE 4
#define CH_U2 2048u      // one 16KB chunk: [2 kt][32 nt][32 lane] uint2 (fp16 b-frags, k32 slab)
#define CH_BYTES 16384u

// dynamic smem layout (bytes)
// mbars: full[4] @ 0..64, empty[4] @ 64..128
#define OFF_T 128u                               // t_range 25 f32
#define OFF_BW 384u                              // float2 (b1, wt)[256] -> 2048B
#define OFF_B2 2432u                             // f32 b2[256] -> 1024B
#define OFF_Z 3584u                              // 128x256 fp16, comp-major tiles = 65536B
#define OFF_H (OFF_Z + 65536u)                   // 69120
#define OFF_RING (OFF_H + 65536u)                // 134656
#define DYN_SMEM (OFF_RING + NSTAGE * CH_BYTES)  // 200192

// prep output: 16 chunks (W1 k32-slabs 0-7, W2 k32-slabs 8-15) of 16KB fp16 b-frag images
__device__ __align__(128) uint2 g_wblk[16 * CH_U2];

// ---------- helpers ----------
__device__ __forceinline__ uint32_t smem_u32(const void* p) {
    uint32_t a;
    asm("{ .reg .u64 t; cvta.to.shared.u64 t, %1; cvt.u32.u64 %0, t; }" : "=r"(a) : "l"(p));
    return a;
}
// pack two f32 -> f16x2 (lo = first arg, hi = second), round-to-nearest
__device__ __forceinline__ uint32_t pack_h2(float lo, float hi) {
    uint32_t r;
    asm("cvt.rn.f16x2.f32 %0, %1, %2;" : "=r"(r) : "f"(hi), "f"(lo));
    return r;
}
// packed fp16x2 tanh (1 MUFU op for 2 values)
__device__ __forceinline__ uint32_t tanh_h2(uint32_t x) {
    uint32_t r;
    asm("tanh.approx.f16x2 %0, %1;" : "=r"(r) : "r"(x));
    return r;
}

#define MBINIT(addr, cnt) \
    asm volatile("mbarrier.init.shared.b64 [%0], %1;" :: "r"(addr), "r"(cnt) : "memory")
#define MB_TX(addr, bytes) \
    asm volatile("mbarrier.arrive.expect_tx.shared.b64 _, [%0], %1;" :: "r"(addr), "r"(bytes) : "memory")
#define MB_ARRIVE(addr) \
    asm volatile("mbarrier.arrive.shared.b64 _, [%0];" :: "r"(addr) : "memory")

#define WAITP(addr, par) do { \
    uint32_t _m = (addr), _p = (par), _d; \
    asm volatile("{\n\t.reg .pred p;\n\t" \
        "mbarrier.try_wait.parity.acquire.cta.shared::cta.b64 p, [%1], %2;\n\t" \
        "selp.b32 %0, 1, 0, p;\n\t}" : "=r"(_d) : "r"(_m), "r"(_p) : "memory"); \
    if (!_d) { \
        asm volatile("{\n\t.reg .pred P1;\n\t" \
            "WL_%=:\n\t" \
            "mbarrier.try_wait.parity.acquire.cta.shared::cta.b64 P1, [%0], %1, 0x989680;\n\t" \
            "@P1 bra.uni WD_%=;\n\tbra.uni WL_%=;\n\tWD_%=:\n\t}" \
            :: "r"(_m), "r"(_p) : "memory"); \
    } \
} while (0)

#define WAITPR(addr, par) do { \
    uint32_t _m = (addr), _p = (par), _d; \
    asm volatile("{\n\t.reg .pred p;\n\t" \
        "mbarrier.try_wait.parity.relaxed.cta.shared::cta.b64 p, [%1], %2, 0x989680;\n\t" \
        "selp.b32 %0, 1, 0, p;\n\t}" : "=r"(_d) : "r"(_m), "r"(_p) : "memory"); \
    if (!_d) { \
        asm volatile("{\n\t.reg .pred P1;\n\t" \
            "WL_%=:\n\t" \
            "mbarrier.try_wait.parity.relaxed.cta.shared::cta.b64 P1, [%0], %1, 0x989680;\n\t" \
            "@P1 bra.uni WD_%=;\n\tbra.uni WL_%=;\n\tWD_%=:\n\t}" \
            :: "r"(_m), "r"(_p) : "memory"); \
    } \
} while (0)

#define BAR1() asm volatile("bar.sync 1, 512;" ::: "memory")

__device__ __forceinline__ void bulk_g2s(uint32_t dst, const void* src, uint32_t bytes, uint32_t mbar) {
    asm volatile(
        "cp.async.bulk.shared::cluster.global.mbarrier::complete_tx::bytes [%0], [%1], %2, [%3];"
        :: "r"(dst), "l"(src), "r"(bytes), "r"(mbar) : "memory");
}

// mma.sync m16n8k16 f16->f32 (g=lane>>2, t=lane&3):
// a0=(g,2t:2t+1) a1=(g+8,2t:2t+1) a2=(g,2t+8:2t+9) a3=(g+8,2t+8:2t+9)  [lo = even k]
// b0=(2t:2t+1, g) b1=(2t+8:2t+9, g)                                     [lo = even k]
// c0=(g,2t) c1=(g,2t+1) c2=(g+8,2t) c3=(g+8,2t+1)
#define MMA16(d, ax, ay, az, aw, bx, by) \
    asm volatile("mma.sync.aligned.m16n8k16.row.col.f32.f16.f16.f32 " \
        "{%0,%1,%2,%3}, {%4,%5,%6,%7}, {%8,%9}, {%0,%1,%2,%3};" \
        : "+f"((d)[0]), "+f"((d)[1]), "+f"((d)[2]), "+f"((d)[3]) \
        : "r"(ax), "r"(ay), "r"(az), "r"(aw), "r"(bx), "r"(by))

// comp-major A-fragment layout: matrix (row 0..127, colpair 0..127) in 16x8cp tiles,
// tile T = (row>>4)*16 + (cp>>3); word = T*128 + comp*32 + lane,
// comp = ((row>>3)&1) + (((cp>>2)&1)<<1), lane = ((row&7)<<2) + (cp&3).
// Epilogue stores hit word == c*32 + own-lane -> conflict-free STS.32.
__device__ __forceinline__ void zh_store_pair(uint32_t* ZB, int row, int cp, uint32_t v) {
    int tile = ((row >> 4) << 4) + (cp >> 3);
    int comp = ((row >> 3) & 1) + (((cp >> 2) & 1) << 1);
    int ln = ((row & 7) << 2) + (cp & 3);
    ZB[tile * 128 + comp * 32 + ln] = v;
}

// ---------- prep: fp16-round + B-frag k32-slab images ----------
// chunk c = mat*8 + slab: B[k][n] = W[k][n], k in [slab*32,+32), n in [0,256)
// uint2 at ((kt*32 + nt)*32 + lane): b0 = {W[kb+2t][n], W[kb+2t+1][n]},
// b1 = {W[kb+2t+8][n], W[kb+2t+9][n]}, kb = slab*32 + kt*16, n = nt*8 + g
extern "C" __global__ void __launch_bounds__(256) ode_prep(
    const float* __restrict__ W1, const float* __restrict__ W2) {
    int c = blockIdx.x, mat = c >> 3, slab = c & 7;
    const float* W = mat ? W2 : W1;
    for (int e = threadIdx.x; e < (int)CH_U2; e += 256) {
        int lane = e & 31, nt = (e >> 5) & 31, kt = e >> 10;
        int g = lane >> 2, t = lane & 3;
        int kb = slab * 32 + kt * 16, n = nt * 8 + g;
        uint2 v;
        v.x = pack_h2(W[(kb + 2 * t) * 256 + n], W[(kb + 2 * t + 1) * 256 + n]);
        v.y = pack_h2(W[(kb + 2 * t + 8) * 256 + n], W[(kb + 2 * t + 9) * 256 + n]);
        g_wblk[c * CH_U2 + e] = v;
    }
}

// ---------- GEMM pass: D[32x64 per warp] += A(src buf) @ B(ring), k=256 over 8 k32 chunks ----------
__device__ __forceinline__ void gemm_pass(
    float (&d)[2][8][4], const char* smem, uint32_t sb, uint32_t a_off,
    int mi, int ni, int lane, uint32_t& cs, uint32_t& cp) {
    const uint32_t* A = (const uint32_t*)(smem + a_off);
    for (int kc = 0; kc < 8; kc++) {
        WAITP(sb + 16u * cs, cp);
        const uint2* Bk = (const uint2*)(smem + OFF_RING + cs * CH_BYTES);
#pragma unroll
        for (int kt = 0; kt < 2; kt++) {
            const int ktile = kc * 2 + kt;
            uint32_t a[2][4];
#pragma unroll
            for (int i = 0; i < 2; i++) {
                const uint32_t* Ab = A + (((mi * 2 + i) * 16 + ktile) * 128) + lane;
                a[i][0] = Ab[0]; a[i][1] = Ab[32]; a[i][2] = Ab[64]; a[i][3] = Ab[96];
            }
            uint2 b[8];
#pragma unroll
            for (int j = 0; j < 8; j++) b[j] = Bk[(kt * 32 + ni * 8 + j) * 32 + lane];
#pragma unroll
            for (int i = 0; i < 2; i++)
#pragma unroll
                for (int j = 0; j < 8; j++)
                    MMA16(d[i][j], a[i][0], a[i][1], a[i][2], a[i][3], b[j].x, b[j].y);
        }
        if (lane == 0) MB_ARRIVE(sb + 64u + 16u * cs);
        cs++; if (cs == NSTAGE) { cs = 0; cp ^= 1; }
    }
}

// ---------- main persistent kernel ----------
// 128 CTAs x 128 rows; warps 0-15 compute (4x4 grid of 32x64 tiles), warp 16 = producer.
// Separate Z/H buffers (2 barriers/step); comp-major layout; f16x2 tanh.
extern "C" __global__ void __launch_bounds__(544, 1) ode_main(
    const float* __restrict__ z0, const float* __restrict__ t_range,
    const float* __restrict__ b1, const float* __restrict__ wt,
    const float* __restrict__ b2, float* __restrict__ out) {
    extern __shared__ char smem[];
    const uint32_t sb = smem_u32(smem);
    const int tid = threadIdx.x, w = tid >> 5, lane = tid & 31;
    const int row0 = blockIdx.x * 128;

    uint32_t* ZB = (uint32_t*)(smem + OFF_Z);
    uint32_t* HB = (uint32_t*)(smem + OFF_H);
    float* sT = (float*)(smem + OFF_T);
    float2* sBW = (float2*)(smem + OFF_BW);
    float* sB2 = (float*)(smem + OFF_B2);

    if (tid == 0) {
        for (int s = 0; s < NSTAGE; s++) {
            MBINIT(sb + 16u * s, 1);         // full: producer MB_TX(1 arrive) + bulk bytes
            MBINIT(sb + 64u + 16u * s, 16);  // empty: one arrive per compute warp
        }
    }
    if (tid < 256) {
        sB2[tid] = b2[tid];
        sBW[tid] = make_float2(b1[tid], wt[tid]);
        if (tid < 25) sT[tid] = t_range[tid];
        // init: z master -> out, fp16 image -> Z (thread owns half a row = 64 col-pairs)
        const int row = tid >> 1, cb = (tid & 1) * 128;
        const float4* zp = (const float4*)(z0 + (size_t)(row0 + row) * 256 + cb);
        float4* op = (float4*)(out + (size_t)(row0 + row) * 256 + cb);
#pragma unroll 4
        for (int q = 0; q < 32; q++) {
            float4 v = zp[q];
            op[q] = v;
            int cp0 = (cb >> 1) + 2 * q;
            zh_store_pair(ZB, row, cp0 + 0, pack_h2(v.x, v.y));
            zh_store_pair(ZB, row, cp0 + 1, pack_h2(v.z, v.w));
        }
    }
    __syncthreads();

    if (w == 16) {
        // ---- producer: 25 steps x 16 chunks (W1 slabs 0-7 then W2 slabs 8-15) ----
        if (lane == 0) {
            uint32_t es = 0, ep = 1;
            for (int i = 0; i < 400; i++) {
                WAITPR(sb + 64u + 16u * es, ep);
                MB_TX(sb + 16u * es, CH_BYTES);
                bulk_g2s(sb + OFF_RING + es * CH_BYTES, g_wblk + (i & 15) * CH_U2,
                         CH_BYTES, sb + 16u * es);
                es++; if (es == NSTAGE) { es = 0; ep ^= 1; }
            }
        }
        return;
    }

    // ---- compute warps ----
    const int mi = w >> 2, ni = w & 3;  // warp tile: rows [mi*32,+32), cols [ni*64,+64)
    const int gid = lane >> 2, tig = lane & 3;
    const float dt = sT[1] - sT[0];
    uint32_t cs = 0, cp = 0;
    float d[2][8][4];

    for (int s = 0; s < 25; s++) {
        const float t = sT[s];
        // ---- GEMM1: D = z @ W1 (reads Z) ----
#pragma unroll
        for (int i = 0; i < 2; i++)
#pragma unroll
            for (int j = 0; j < 8; j++)
#pragma unroll
                for (int r = 0; r < 4; r++) d[i][j][r] = 0.0f;
        gemm_pass(d, smem, sb, OFF_Z, mi, ni, lane, cs, cp);
        // ---- h = tanh(D + b1 + t*wt) -> H (packed f16x2 tanh; no barrier: H != Z) ----
#pragma unroll
        for (int i = 0; i < 2; i++)
#pragma unroll
            for (int j = 0; j < 8; j++) {
                const int col = ni * 64 + j * 8 + 2 * tig;
                const int cpair = ni * 32 + j * 4 + tig;
                const float2 bw0 = sBW[col], bw1 = sBW[col + 1];
                const int row = mi * 32 + i * 16 + gid;
                float x0 = d[i][j][0] + bw0.x + t * bw0.y;
                float x1 = d[i][j][1] + bw1.x + t * bw1.y;
                zh_store_pair(HB, row, cpair, tanh_h2(pack_h2(x0, x1)));
                float x2 = d[i][j][2] + bw0.x + t * bw0.y;
                float x3 = d[i][j][3] + bw1.x + t * bw1.y;
                zh_store_pair(HB, row + 8, cpair, tanh_h2(pack_h2(x2, x3)));
            }
        BAR1();  // H fully written (also implies all Z reads done)
        // ---- GEMM2: D = h @ W2 (reads H) ----
#pragma unroll
        for (int i = 0; i < 2; i++)
#pragma unroll
            for (int j = 0; j < 8; j++)
#pragma unroll
                for (int r = 0; r < 4; r++) d[i][j][r] = 0.0f;
        gemm_pass(d, smem, sb, OFF_H, mi, ni, lane, cs, cp);
        // ---- z update: z += dt*(D + b2) -> out + Z (no barrier: Z != H) ----
#pragma unroll
        for (int i = 0; i < 2; i++)
#pragma unroll
            for (int j = 0; j < 8; j++) {
                const int col = ni * 64 + j * 8 + 2 * tig;
                const int cpair = ni * 32 + j * 4 + tig;
#pragma unroll
                for (int rp = 0; rp < 2; rp++) {
                    int row = mi * 32 + i * 16 + gid + rp * 8;
                    size_t g = (size_t)(row0 + row) * 256 + col;
                    float2 zo = *(const float2*)(out + g);
                    float zn0 = fmaf(dt, d[i][j][2 * rp + 0] + sB2[col + 0], zo.x);
                    float zn1 = fmaf(dt, d[i][j][2 * rp + 1] + sB2[col + 1], zo.y);
                    *(float2*)(out + g) = make_float2(zn0, zn1);
                    zh_store_pair(ZB, row, cpair, pack_h2(zn0, zn1));
                }
            }
        BAR1();  // Z fully written (also implies all H reads done)
    }
}

extern "C" void kernel_launch(void* const* d_in, const int* in_sizes, int n_in,
                              void* d_out, int out_size) {
    const float* z0 = (const float*)d_in[0];
    const float* t_range = (const float*)d_in[1];
    const float* W1 = (const float*)d_in[2];
    const float* b1 = (const float*)d_in[3];
    const float* wt = (const float*)d_in[4];
    const float* W2 = (const float*)d_in[5];
    const float* b2 = (const float*)d_in[6];
    float* out = (float*)d_out;

    cudaFuncSetAttribute(ode_main, cudaFuncAttributeMaxDynamicSharedMemorySize, DYN_SMEM);
    ode_prep<<<16, 256>>>(W1, W2);
    ode_main<<<128, 544, DYN_SMEM>>>(z0, t_range, b1, wt, b2, out);
}